// round 13
// baseline (speedup 1.0000x reference)
#include <cuda_runtime.h>
#include <cuda_bf16.h>
#include <math.h>
#include <float.h>
#include <stdint.h>

#define B_   2
#define S_   2048
#define E_   2048
#define H_   32
#define KV_  8
#define D_   128
#define NTOK (B_ * S_)
#define HD_  (H_ * D_)   // 4096
#define KVD_ (KV_ * D_)  // 1024

// ---------------------------------------------------------------------------
// Scratch
// ---------------------------------------------------------------------------
__device__ float g_q[(size_t)NTOK * HD_];
__device__ float g_k[(size_t)NTOK * KVD_];

__device__ __nv_bfloat16 g_xh[(size_t)NTOK * E_],  g_xl[(size_t)NTOK * E_];
__device__ __nv_bfloat16 g_ch[(size_t)NTOK * HD_], g_cl[(size_t)NTOK * HD_];
__device__ __nv_bfloat16 g_wqh[(size_t)HD_ * E_],  g_wql[(size_t)HD_ * E_];
__device__ __nv_bfloat16 g_wkh[(size_t)KVD_ * E_], g_wkl[(size_t)KVD_ * E_];
__device__ __nv_bfloat16 g_wvh[(size_t)KVD_ * E_], g_wvl[(size_t)KVD_ * E_];
__device__ __nv_bfloat16 g_woh[(size_t)E_ * HD_],  g_wol[(size_t)E_ * HD_];
__device__ __nv_bfloat16 g_qh[(size_t)NTOK * HD_],  g_ql[(size_t)NTOK * HD_];
__device__ __nv_bfloat16 g_kh[(size_t)NTOK * KVD_], g_kl[(size_t)NTOK * KVD_];
__device__ __nv_bfloat16 g_vh[(size_t)NTOK * KVD_], g_vl[(size_t)NTOK * KVD_];

// ---------------------------------------------------------------------------
// Primitives (base target, compile at compute_103)
// ---------------------------------------------------------------------------
__device__ __forceinline__ uint32_t smem_u32(const void* p) {
    uint32_t a;
    asm("{ .reg .u64 t; cvta.to.shared.u64 t, %1; cvt.u32.u64 %0, t; }" : "=r"(a) : "l"(p));
    return a;
}
__device__ __forceinline__ void ldsm4(uint32_t& r0, uint32_t& r1, uint32_t& r2,
                                      uint32_t& r3, uint32_t addr) {
    asm volatile("ldmatrix.sync.aligned.m8n8.x4.shared.b16 {%0,%1,%2,%3}, [%4];"
                 : "=r"(r0), "=r"(r1), "=r"(r2), "=r"(r3) : "r"(addr));
}
__device__ __forceinline__ void ldsm4t(uint32_t& r0, uint32_t& r1, uint32_t& r2,
                                       uint32_t& r3, uint32_t addr) {
    asm volatile("ldmatrix.sync.aligned.m8n8.x4.trans.shared.b16 {%0,%1,%2,%3}, [%4];"
                 : "=r"(r0), "=r"(r1), "=r"(r2), "=r"(r3) : "r"(addr));
}
__device__ __forceinline__ void mma_bf16(float* c, uint32_t a0, uint32_t a1,
                                         uint32_t a2, uint32_t a3,
                                         uint32_t b0, uint32_t b1) {
    asm volatile(
        "mma.sync.aligned.m16n8k16.row.col.f32.bf16.bf16.f32 "
        "{%0,%1,%2,%3}, {%4,%5,%6,%7}, {%8,%9}, {%0,%1,%2,%3};"
        : "+f"(c[0]), "+f"(c[1]), "+f"(c[2]), "+f"(c[3])
        : "r"(a0), "r"(a1), "r"(a2), "r"(a3), "r"(b0), "r"(b1));
}

// ---------------------------------------------------------------------------
// split: fp32 -> (hi, lo) bf16
// ---------------------------------------------------------------------------
__global__ __launch_bounds__(256) void split_kernel(
    const float* __restrict__ src, __nv_bfloat16* __restrict__ h,
    __nv_bfloat16* __restrict__ l, int n)
{
    int i = blockIdx.x * 256 + threadIdx.x;
    if (i < n) {
        float v = src[i];
        __nv_bfloat16 hh = __float2bfloat16(v);
        h[i] = hh;
        l[i] = __float2bfloat16(v - __bfloat162float(hh));
    }
}

// ---------------------------------------------------------------------------
// transpose + split: W [K][N] fp32 -> Th/Tl [N][K] bf16
// ---------------------------------------------------------------------------
__global__ __launch_bounds__(256) void transpose_split_kernel(
    const float* __restrict__ W, __nv_bfloat16* __restrict__ Th,
    __nv_bfloat16* __restrict__ Tl, int K, int N)
{
    __shared__ float t[32][33];
    int n = blockIdx.x * 32 + threadIdx.x;
    int k0 = blockIdx.y * 32;
    for (int j = threadIdx.y; j < 32; j += 8)
        t[j][threadIdx.x] = W[(size_t)(k0 + j) * N + n];
    __syncthreads();
    int k = k0 + threadIdx.x;
    for (int j = threadIdx.y; j < 32; j += 8) {
        float v = t[threadIdx.x][j];
        int nn = blockIdx.x * 32 + j;
        __nv_bfloat16 hh = __float2bfloat16(v);
        Th[(size_t)nn * K + k] = hh;
        Tl[(size_t)nn * K + k] = __float2bfloat16(v - __bfloat162float(hh));
    }
}

// ---------------------------------------------------------------------------
// HMMA GEMM (R5-verified synchronous mainloop, BK=64). 3-term split-bf16,
// fp32 accum. split_out: write (Ch,Cl) bf16 instead of fp32 C.
// ---------------------------------------------------------------------------
#define AS_B   144                 // 128B row + 16B pad
#define TILE_B (128 * AS_B)        // 18432
#define GSM_AH 0
#define GSM_AL (TILE_B)
#define GSM_BH (2 * TILE_B)
#define GSM_BL (3 * TILE_B)
#define GSM_TOTAL (4 * TILE_B)     // 73728

__global__ __launch_bounds__(256, 2) void gemm_hmma_kernel(
    const __nv_bfloat16* __restrict__ Ah, const __nv_bfloat16* __restrict__ Al,
    const __nv_bfloat16* __restrict__ Bh, const __nv_bfloat16* __restrict__ Bl,
    const float* __restrict__ bias, float* __restrict__ C,
    __nv_bfloat16* __restrict__ Ch, __nv_bfloat16* __restrict__ Cl,
    int M, int N, int K, int split_out)
{
    extern __shared__ char smem[];
    const uint32_t sbase = smem_u32(smem);
    const int tid  = threadIdx.x;
    const int wid  = tid >> 5, lane = tid & 31;
    const int m0   = blockIdx.y * 128, n0 = blockIdx.x * 128;
    const int wm   = (wid >> 2) * 64;
    const int wn   = (wid & 3) * 32;

    float acc[4][4][4];
#pragma unroll
    for (int i = 0; i < 4; i++)
#pragma unroll
        for (int j = 0; j < 4; j++)
#pragma unroll
            for (int f = 0; f < 4; f++) acc[i][j][f] = 0.f;

    const int lr  = tid >> 3;
    const int lcB = (tid & 7) << 4;

    const int a_row = wm + (lane & 7) + ((lane >> 3) & 1) * 8;
    const int a_kB  = (lane >> 4) * 16;
    const int seg   = lane >> 3;
    const int b_row = wn + (lane & 7) + (seg >> 1) * 8;
    const int b_kB  = (seg & 1) * 16;

    for (int k0 = 0; k0 < K; k0 += 64) {
#pragma unroll
        for (int t = 0; t < 4; t++) {
            int r = lr + t * 32;
            size_t ga = ((size_t)(m0 + r) * K + k0) * 2 + lcB;
            size_t gb = ((size_t)(n0 + r) * K + k0) * 2 + lcB;
            int so = r * AS_B + lcB;
            *(uint4*)(smem + GSM_AH + so) = *(const uint4*)((const char*)Ah + ga);
            *(uint4*)(smem + GSM_AL + so) = *(const uint4*)((const char*)Al + ga);
            *(uint4*)(smem + GSM_BH + so) = *(const uint4*)((const char*)Bh + gb);
            *(uint4*)(smem + GSM_BL + so) = *(const uint4*)((const char*)Bl + gb);
        }
        __syncthreads();

#pragma unroll
        for (int ks = 0; ks < 4; ks++) {
            const int kB = ks * 32;
            uint32_t af[4][4], bh[4][2], bl[4][2];
#pragma unroll
            for (int mt = 0; mt < 4; mt++)
                ldsm4(af[mt][0], af[mt][1], af[mt][2], af[mt][3],
                      sbase + GSM_AH + (a_row + mt * 16) * AS_B + kB + a_kB);
#pragma unroll
            for (int bt = 0; bt < 2; bt++) {
                uint32_t r0, r1, r2, r3;
                ldsm4(r0, r1, r2, r3,
                      sbase + GSM_BH + (b_row + bt * 16) * AS_B + kB + b_kB);
                bh[bt * 2][0] = r0; bh[bt * 2][1] = r1;
                bh[bt * 2 + 1][0] = r2; bh[bt * 2 + 1][1] = r3;
            }
#pragma unroll
            for (int mt = 0; mt < 4; mt++)
#pragma unroll
                for (int nt = 0; nt < 4; nt++)
                    mma_bf16(acc[mt][nt], af[mt][0], af[mt][1], af[mt][2],
                             af[mt][3], bh[nt][0], bh[nt][1]);
#pragma unroll
            for (int bt = 0; bt < 2; bt++) {
                uint32_t r0, r1, r2, r3;
                ldsm4(r0, r1, r2, r3,
                      sbase + GSM_BL + (b_row + bt * 16) * AS_B + kB + b_kB);
                bl[bt * 2][0] = r0; bl[bt * 2][1] = r1;
                bl[bt * 2 + 1][0] = r2; bl[bt * 2 + 1][1] = r3;
            }
#pragma unroll
            for (int mt = 0; mt < 4; mt++)
#pragma unroll
                for (int nt = 0; nt < 4; nt++)
                    mma_bf16(acc[mt][nt], af[mt][0], af[mt][1], af[mt][2],
                             af[mt][3], bl[nt][0], bl[nt][1]);
#pragma unroll
            for (int mt = 0; mt < 4; mt++)
                ldsm4(af[mt][0], af[mt][1], af[mt][2], af[mt][3],
                      sbase + GSM_AL + (a_row + mt * 16) * AS_B + kB + a_kB);
#pragma unroll
            for (int mt = 0; mt < 4; mt++)
#pragma unroll
                for (int nt = 0; nt < 4; nt++)
                    mma_bf16(acc[mt][nt], af[mt][0], af[mt][1], af[mt][2],
                             af[mt][3], bh[nt][0], bh[nt][1]);
        }
        __syncthreads();
    }

#pragma unroll
    for (int nt = 0; nt < 4; nt++) {
        int col = n0 + wn + nt * 8 + (lane & 3) * 2;
        float b0 = bias ? bias[col] : 0.f;
        float b1 = bias ? bias[col + 1] : 0.f;
#pragma unroll
        for (int mt = 0; mt < 4; mt++) {
            int row = m0 + wm + mt * 16 + (lane >> 2);
            float v00 = acc[mt][nt][0] + b0, v01 = acc[mt][nt][1] + b1;
            float v10 = acc[mt][nt][2] + b0, v11 = acc[mt][nt][3] + b1;
            if (!split_out) {
                *(float2*)(C + (size_t)row * N + col) = make_float2(v00, v01);
                *(float2*)(C + (size_t)(row + 8) * N + col) = make_float2(v10, v11);
            } else {
                __nv_bfloat16 h00 = __float2bfloat16(v00), h01 = __float2bfloat16(v01);
                __nv_bfloat16 h10 = __float2bfloat16(v10), h11 = __float2bfloat16(v11);
                *(__nv_bfloat162*)(Ch + (size_t)row * N + col) = __nv_bfloat162(h00, h01);
                *(__nv_bfloat162*)(Ch + (size_t)(row + 8) * N + col) = __nv_bfloat162(h10, h11);
                *(__nv_bfloat162*)(Cl + (size_t)row * N + col) =
                    __nv_bfloat162(__float2bfloat16(v00 - __bfloat162float(h00)),
                                   __float2bfloat16(v01 - __bfloat162float(h01)));
                *(__nv_bfloat162*)(Cl + (size_t)(row + 8) * N + col) =
                    __nv_bfloat162(__float2bfloat16(v10 - __bfloat162float(h10)),
                                   __float2bfloat16(v11 - __bfloat162float(h11)));
            }
        }
    }
}

// ---------------------------------------------------------------------------
// Fused RMSNorm + RoPE -> split-bf16 output
// ---------------------------------------------------------------------------
__global__ __launch_bounds__(256) void rmsrope_split_kernel(
    const float* __restrict__ t, const float* __restrict__ cosT,
    const float* __restrict__ sinT, const float* __restrict__ scale, int heads,
    __nv_bfloat16* __restrict__ oh, __nv_bfloat16* __restrict__ ol)
{
    int gw   = (blockIdx.x * 256 + threadIdx.x) >> 5;
    int lane = threadIdx.x & 31;
    if (gw >= NTOK * heads) return;
    int token = gw / heads;
    int h     = gw - token * heads;
    int s     = token & (S_ - 1);

    const float* row = t + ((size_t)token * heads + h) * D_;
    float4 x = *(const float4*)(row + lane * 4);

    float ss = fmaf(x.x, x.x, fmaf(x.y, x.y, fmaf(x.z, x.z, x.w * x.w)));
#pragma unroll
    for (int o = 16; o; o >>= 1) ss += __shfl_xor_sync(0xffffffffu, ss, o);
    float r = rsqrtf(ss * (1.0f / D_) + 1e-6f);

    float4 sc = *(const float4*)(scale + lane * 4);
    float4 y;
    y.x = x.x * r * sc.x; y.y = x.y * r * sc.y;
    y.z = x.z * r * sc.z; y.w = x.w * r * sc.w;

    float4 p;
    p.x = __shfl_xor_sync(0xffffffffu, y.x, 16);
    p.y = __shfl_xor_sync(0xffffffffu, y.y, 16);
    p.z = __shfl_xor_sync(0xffffffffu, y.z, 16);
    p.w = __shfl_xor_sync(0xffffffffu, y.w, 16);

    float4 c  = *(const float4*)(cosT + (size_t)s * D_ + lane * 4);
    float4 sn = *(const float4*)(sinT + (size_t)s * D_ + lane * 4);
    float sg  = (lane < 16) ? -1.f : 1.f;

    float o0 = fmaf(y.x, c.x, sg * p.x * sn.x);
    float o1 = fmaf(y.y, c.y, sg * p.y * sn.y);
    float o2 = fmaf(y.z, c.z, sg * p.z * sn.z);
    float o3 = fmaf(y.w, c.w, sg * p.w * sn.w);

    size_t off = ((size_t)token * heads + h) * D_ + lane * 4;
    __nv_bfloat16 h0 = __float2bfloat16(o0), h1 = __float2bfloat16(o1);
    __nv_bfloat16 h2 = __float2bfloat16(o2), h3 = __float2bfloat16(o3);
    *(__nv_bfloat162*)(oh + off)     = __nv_bfloat162(h0, h1);
    *(__nv_bfloat162*)(oh + off + 2) = __nv_bfloat162(h2, h3);
    *(__nv_bfloat162*)(ol + off) =
        __nv_bfloat162(__float2bfloat16(o0 - __bfloat162float(h0)),
                       __float2bfloat16(o1 - __bfloat162float(h1)));
    *(__nv_bfloat162*)(ol + off + 2) =
        __nv_bfloat162(__float2bfloat16(o2 - __bfloat162float(h2)),
                       __float2bfloat16(o3 - __bfloat162float(h3)));
}

// ---------------------------------------------------------------------------
// Flash attention, HMMA bf16 3-term split, causal, GQA.
// 64 q-rows/block, k-tiles of 64, 8 warps. Writes split-bf16 ctx.
// ---------------------------------------------------------------------------
#define QK_STRIDE 272
#define P_STRIDE  144
#define ASM_QH  0
#define ASM_QL  (ASM_QH + 64 * QK_STRIDE)
#define ASM_KH  (ASM_QL + 64 * QK_STRIDE)
#define ASM_KL  (ASM_KH + 64 * QK_STRIDE)
#define ASM_VH  (ASM_KL + 64 * QK_STRIDE)
#define ASM_VL  (ASM_VH + 64 * QK_STRIDE)
#define ASM_PH  (ASM_VL + 64 * QK_STRIDE)
#define ASM_PL  (ASM_PH + 64 * P_STRIDE)
#define ASM_S   (ASM_PL + 64 * P_STRIDE)
#define ASM_M   (ASM_S + 64 * 66 * 4)
#define ASM_L   (ASM_M + 256)
#define ASM_F   (ASM_L + 256)
#define ASM_TOTAL (ASM_F + 256)

__global__ __launch_bounds__(256, 1) void attn_hmma_kernel(
    const __nv_bfloat16* __restrict__ qh, const __nv_bfloat16* __restrict__ ql,
    const __nv_bfloat16* __restrict__ kh, const __nv_bfloat16* __restrict__ kl,
    const __nv_bfloat16* __restrict__ vh, const __nv_bfloat16* __restrict__ vl,
    __nv_bfloat16* __restrict__ ch, __nv_bfloat16* __restrict__ cl)
{
    extern __shared__ char smem[];
    const uint32_t sbase = smem_u32(smem);
    float* sS = (float*)(smem + ASM_S);
    float* sM = (float*)(smem + ASM_M);
    float* sL = (float*)(smem + ASM_L);
    float* sF = (float*)(smem + ASM_F);

    const int tid = threadIdx.x, wid = tid >> 5, lane = tid & 31;
    const int qt = blockIdx.x, h = blockIdx.y, b = blockIdx.z;
    const int kvh  = h >> 2;
    const int tok0 = b * S_ + qt * 64;

    const int mr = wid & 3;
    const int nc = wid >> 2;

    for (int i = tid; i < 64 * 16; i += 256) {
        int r = i >> 4, c = i & 15;
        size_t g = (size_t)(tok0 + r) * HD_ + h * D_ + c * 8;
        *(uint4*)(smem + ASM_QH + r * QK_STRIDE + c * 16) = *(const uint4*)(qh + g);
        *(uint4*)(smem + ASM_QL + r * QK_STRIDE + c * 16) = *(const uint4*)(ql + g);
    }
    if (tid < 64) { sM[tid] = -FLT_MAX; sL[tid] = 0.f; }

    float ctxacc[8][4];
#pragma unroll
    for (int i = 0; i < 8; i++)
#pragma unroll
        for (int f = 0; f < 4; f++) ctxacc[i][f] = 0.f;

    const int a_row = (lane & 7) + ((lane >> 3) & 1) * 8;
    const int a_kB  = (lane >> 4) * 16;
    const int seg   = lane >> 3;
    const int b_row = (lane & 7) + (seg >> 1) * 8;
    const int b_kB  = (seg & 1) * 16;
    const int t_row = (lane & 7) + (seg & 1) * 8;
    const int t_cB  = (seg >> 1) * 16;

    const float rsc = 0.08838834764831845f;
    const int row_a = mr * 16 + (lane >> 2);

    for (int kt = 0; kt <= qt; kt++) {
        const int ktok0 = b * S_ + kt * 64;
        __syncthreads();
        for (int i = tid; i < 64 * 16; i += 256) {
            int r = i >> 4, c = i & 15;
            size_t g = (size_t)(ktok0 + r) * KVD_ + kvh * D_ + c * 8;
            *(uint4*)(smem + ASM_KH + r * QK_STRIDE + c * 16) = *(const uint4*)(kh + g);
            *(uint4*)(smem + ASM_KL + r * QK_STRIDE + c * 16) = *(const uint4*)(kl + g);
            *(uint4*)(smem + ASM_VH + r * QK_STRIDE + c * 16) = *(const uint4*)(vh + g);
            *(uint4*)(smem + ASM_VL + r * QK_STRIDE + c * 16) = *(const uint4*)(vl + g);
        }
        __syncthreads();

        float sacc[4][4];
#pragma unroll
        for (int i = 0; i < 4; i++)
#pragma unroll
            for (int f = 0; f < 4; f++) sacc[i][f] = 0.f;

#pragma unroll
        for (int ks = 0; ks < 8; ks++) {
            const int kB = ks * 32;
            uint32_t ah[4], al[4];
            ldsm4(ah[0], ah[1], ah[2], ah[3],
                  sbase + ASM_QH + (mr * 16 + a_row) * QK_STRIDE + kB + a_kB);
            ldsm4(al[0], al[1], al[2], al[3],
                  sbase + ASM_QL + (mr * 16 + a_row) * QK_STRIDE + kB + a_kB);
#pragma unroll
            for (int bt = 0; bt < 2; bt++) {
                uint32_t r0, r1, r2, r3;
                ldsm4(r0, r1, r2, r3,
                      sbase + ASM_KH + (nc * 32 + bt * 16 + b_row) * QK_STRIDE + kB + b_kB);
                mma_bf16(sacc[bt * 2],     ah[0], ah[1], ah[2], ah[3], r0, r1);
                mma_bf16(sacc[bt * 2 + 1], ah[0], ah[1], ah[2], ah[3], r2, r3);
                mma_bf16(sacc[bt * 2],     al[0], al[1], al[2], al[3], r0, r1);
                mma_bf16(sacc[bt * 2 + 1], al[0], al[1], al[2], al[3], r2, r3);
                uint32_t s0, s1, s2, s3;
                ldsm4(s0, s1, s2, s3,
                      sbase + ASM_KL + (nc * 32 + bt * 16 + b_row) * QK_STRIDE + kB + b_kB);
                mma_bf16(sacc[bt * 2],     ah[0], ah[1], ah[2], ah[3], s0, s1);
                mma_bf16(sacc[bt * 2 + 1], ah[0], ah[1], ah[2], ah[3], s2, s3);
            }
        }
#pragma unroll
        for (int nt = 0; nt < 4; nt++) {
            int col = nc * 32 + nt * 8 + (lane & 3) * 2;
            *(float2*)&sS[row_a * 66 + col] =
                make_float2(sacc[nt][0] * rsc, sacc[nt][1] * rsc);
            *(float2*)&sS[(row_a + 8) * 66 + col] =
                make_float2(sacc[nt][2] * rsc, sacc[nt][3] * rsc);
        }
        __syncthreads();

        {
            const int r = tid >> 2, q4 = tid & 3;
            const int j0 = q4 * 16;
            const bool diag = (kt == qt);
            float mold = sM[r];
            float sv[16];
            float tm = -FLT_MAX;
#pragma unroll
            for (int jj = 0; jj < 16; jj++) {
                float v = sS[r * 66 + j0 + jj];
                if (diag && (j0 + jj) > r) v = -FLT_MAX;
                sv[jj] = v;
                tm = fmaxf(tm, v);
            }
            tm = fmaxf(tm, __shfl_xor_sync(0xffffffffu, tm, 1));
            tm = fmaxf(tm, __shfl_xor_sync(0xffffffffu, tm, 2));
            tm = fmaxf(tm, mold);
            float ps = 0.f;
            __nv_bfloat16* ph = (__nv_bfloat16*)(smem + ASM_PH + r * P_STRIDE) + j0;
            __nv_bfloat16* pl = (__nv_bfloat16*)(smem + ASM_PL + r * P_STRIDE) + j0;
#pragma unroll
            for (int jj = 0; jj < 16; jj++) {
                float p = __expf(sv[jj] - tm);
                ps += p;
                __nv_bfloat16 hh = __float2bfloat16(p);
                ph[jj] = hh;
                pl[jj] = __float2bfloat16(p - __bfloat162float(hh));
            }
            ps += __shfl_xor_sync(0xffffffffu, ps, 1);
            ps += __shfl_xor_sync(0xffffffffu, ps, 2);
            if (q4 == 0) {
                float fsc = __expf(mold - tm);
                sM[r] = tm;
                sL[r] = sL[r] * fsc + ps;
                sF[r] = fsc;
            }
        }
        __syncthreads();

        {
            float f0 = sF[row_a], f1 = sF[row_a + 8];
#pragma unroll
            for (int nt = 0; nt < 8; nt++) {
                ctxacc[nt][0] *= f0; ctxacc[nt][1] *= f0;
                ctxacc[nt][2] *= f1; ctxacc[nt][3] *= f1;
            }
        }
#pragma unroll
        for (int ks = 0; ks < 4; ks++) {
            const int kB = ks * 32;
            uint32_t ph4[4], pl4[4];
            ldsm4(ph4[0], ph4[1], ph4[2], ph4[3],
                  sbase + ASM_PH + (mr * 16 + a_row) * P_STRIDE + kB + a_kB);
            ldsm4(pl4[0], pl4[1], pl4[2], pl4[3],
                  sbase + ASM_PL + (mr * 16 + a_row) * P_STRIDE + kB + a_kB);
#pragma unroll
            for (int bt = 0; bt < 4; bt++) {
                uint32_t r0, r1, r2, r3;
                ldsm4t(r0, r1, r2, r3,
                       sbase + ASM_VH + (ks * 16 + t_row) * QK_STRIDE
                             + nc * 128 + bt * 32 + t_cB);
                mma_bf16(ctxacc[bt * 2],     ph4[0], ph4[1], ph4[2], ph4[3], r0, r1);
                mma_bf16(ctxacc[bt * 2 + 1], ph4[0], ph4[1], ph4[2], ph4[3], r2, r3);
                mma_bf16(ctxacc[bt * 2],     pl4[0], pl4[1], pl4[2], pl4[3], r0, r1);
                mma_bf16(ctxacc[bt * 2 + 1], pl4[0], pl4[1], pl4[2], pl4[3], r2, r3);
                uint32_t s0, s1, s2, s3;
                ldsm4t(s0, s1, s2, s3,
                       sbase + ASM_VL + (ks * 16 + t_row) * QK_STRIDE
                             + nc * 128 + bt * 32 + t_cB);
                mma_bf16(ctxacc[bt * 2],     ph4[0], ph4[1], ph4[2], ph4[3], s0, s1);
                mma_bf16(ctxacc[bt * 2 + 1], ph4[0], ph4[1], ph4[2], ph4[3], s2, s3);
            }
        }
    }

    __syncthreads();
    const float inv0 = 1.0f / sL[row_a];
    const float inv1 = 1.0f / sL[row_a + 8];
#pragma unroll
    for (int nt = 0; nt < 8; nt++) {
        int col = nc * 64 + nt * 8 + (lane & 3) * 2;
        size_t o0 = (size_t)(tok0 + row_a) * HD_ + h * D_ + col;
        size_t o1 = (size_t)(tok0 + row_a + 8) * HD_ + h * D_ + col;
        float v00 = ctxacc[nt][0] * inv0, v01 = ctxacc[nt][1] * inv0;
        float v10 = ctxacc[nt][2] * inv1, v11 = ctxacc[nt][3] * inv1;
        __nv_bfloat16 h00 = __float2bfloat16(v00), h01 = __float2bfloat16(v01);
        __nv_bfloat16 h10 = __float2bfloat16(v10), h11 = __float2bfloat16(v11);
        *(__nv_bfloat162*)(ch + o0) = __nv_bfloat162(h00, h01);
        *(__nv_bfloat162*)(ch + o1) = __nv_bfloat162(h10, h11);
        *(__nv_bfloat162*)(cl + o0) =
            __nv_bfloat162(__float2bfloat16(v00 - __bfloat162float(h00)),
                           __float2bfloat16(v01 - __bfloat162float(h01)));
        *(__nv_bfloat162*)(cl + o1) =
            __nv_bfloat162(__float2bfloat16(v10 - __bfloat162float(h10)),
                           __float2bfloat16(v11 - __bfloat162float(h11)));
    }
}

// ---------------------------------------------------------------------------
// Inputs: 0:x 1:mask 2:cos 3:sin 4:Wq 5:bq 6:Wk 7:bk 8:Wv 9:bv 10:Wo 11:qs 12:ks
// ---------------------------------------------------------------------------
extern "C" void kernel_launch(void* const* d_in, const int* in_sizes, int n_in,
                              void* d_out, int out_size)
{
    const float* x    = (const float*)d_in[0];
    const float* cosT = (const float*)d_in[2];
    const float* sinT = (const float*)d_in[3];
    const float* Wq   = (const float*)d_in[4];
    const float* bq   = (const float*)d_in[5];
    const float* Wk   = (const float*)d_in[6];
    const float* bk   = (const float*)d_in[7];
    const float* Wv   = (const float*)d_in[8];
    const float* bv   = (const float*)d_in[9];
    const float* Wo   = (const float*)d_in[10];
    const float* qs   = (const float*)d_in[11];
    const float* ks   = (const float*)d_in[12];
    float* out = (float*)d_out;
    (void)in_sizes; (void)n_in; (void)out_size;

    float *dq, *dk;
    cudaGetSymbolAddress((void**)&dq, g_q);
    cudaGetSymbolAddress((void**)&dk, g_k);
    __nv_bfloat16 *xh, *xl, *ch, *cl, *wqh, *wql, *wkh, *wkl, *wvh, *wvl, *woh, *wol;
    __nv_bfloat16 *aqh, *aql, *akh, *akl, *avh, *avl;
    cudaGetSymbolAddress((void**)&xh, g_xh);   cudaGetSymbolAddress((void**)&xl, g_xl);
    cudaGetSymbolAddress((void**)&ch, g_ch);   cudaGetSymbolAddress((void**)&cl, g_cl);
    cudaGetSymbolAddress((void**)&wqh, g_wqh); cudaGetSymbolAddress((void**)&wql, g_wql);
    cudaGetSymbolAddress((void**)&wkh, g_wkh); cudaGetSymbolAddress((void**)&wkl, g_wkl);
    cudaGetSymbolAddress((void**)&wvh, g_wvh); cudaGetSymbolAddress((void**)&wvl, g_wvl);
    cudaGetSymbolAddress((void**)&woh, g_woh); cudaGetSymbolAddress((void**)&wol, g_wol);
    cudaGetSymbolAddress((void**)&aqh, g_qh);  cudaGetSymbolAddress((void**)&aql, g_ql);
    cudaGetSymbolAddress((void**)&akh, g_kh);  cudaGetSymbolAddress((void**)&akl, g_kl);
    cudaGetSymbolAddress((void**)&avh, g_vh);  cudaGetSymbolAddress((void**)&avl, g_vl);

    cudaFuncSetAttribute(attn_hmma_kernel, cudaFuncAttributeMaxDynamicSharedMemorySize,
                         ASM_TOTAL);
    cudaFuncSetAttribute(gemm_hmma_kernel, cudaFuncAttributeMaxDynamicSharedMemorySize,
                         GSM_TOTAL);

    dim3 t256(256);
    dim3 t32x8(32, 8);

    split_kernel<<<(NTOK * E_) / 256, t256>>>(x, xh, xl, NTOK * E_);
    transpose_split_kernel<<<dim3(HD_ / 32, E_ / 32), t32x8>>>(Wq, wqh, wql, E_, HD_);
    transpose_split_kernel<<<dim3(KVD_ / 32, E_ / 32), t32x8>>>(Wk, wkh, wkl, E_, KVD_);
    transpose_split_kernel<<<dim3(KVD_ / 32, E_ / 32), t32x8>>>(Wv, wvh, wvl, E_, KVD_);
    // projections (V writes split bf16 directly)
    gemm_hmma_kernel<<<dim3(HD_ / 128, NTOK / 128), t256, GSM_TOTAL>>>(
        xh, xl, wqh, wql, bq, dq, nullptr, nullptr, NTOK, HD_, E_, 0);
    gemm_hmma_kernel<<<dim3(KVD_ / 128, NTOK / 128), t256, GSM_TOTAL>>>(
        xh, xl, wkh, wkl, bk, dk, nullptr, nullptr, NTOK, KVD_, E_, 0);
    gemm_hmma_kernel<<<dim3(KVD_ / 128, NTOK / 128), t256, GSM_TOTAL>>>(
        xh, xl, wvh, wvl, bv, nullptr, avh, avl, NTOK, KVD_, E_, 1);
    transpose_split_kernel<<<dim3(E_ / 32, HD_ / 32), t32x8>>>(Wo, woh, wol, HD_, E_);
    // RMSNorm + RoPE -> split bf16
    rmsrope_split_kernel<<<(NTOK * H_ * 32) / 256, t256>>>(dq, cosT, sinT, qs, H_, aqh, aql);
    rmsrope_split_kernel<<<(NTOK * KV_ * 32) / 256, t256>>>(dk, cosT, sinT, ks, KV_, akh, akl);
    // attention -> split bf16 ctx
    attn_hmma_kernel<<<dim3(S_ / 64, H_, B_), t256, ASM_TOTAL>>>(
        aqh, aql, akh, akl, avh, avl, ch, cl);
    // output projection
    gemm_hmma_kernel<<<dim3(E_ / 128, NTOK / 128), t256, GSM_TOTAL>>>(
        ch, cl, woh, wol, nullptr, out, nullptr, nullptr, NTOK, E_, HD_, 0);
}

// round 14
// speedup vs baseline: 1.6349x; 1.6349x over previous
#include <cuda_runtime.h>
#include <cuda_bf16.h>
#include <math.h>
#include <float.h>
#include <stdint.h>

#define B_   2
#define S_   2048
#define E_   2048
#define H_   32
#define KV_  8
#define D_   128
#define NTOK (B_ * S_)
#define HD_  (H_ * D_)   // 4096
#define KVD_ (KV_ * D_)  // 1024

// ---------------------------------------------------------------------------
// Scratch
// ---------------------------------------------------------------------------
__device__ float g_q[(size_t)NTOK * HD_];
__device__ float g_k[(size_t)NTOK * KVD_];

__device__ __nv_bfloat16 g_xh[(size_t)NTOK * E_],  g_xl[(size_t)NTOK * E_];
__device__ __nv_bfloat16 g_ch[(size_t)NTOK * HD_], g_cl[(size_t)NTOK * HD_];
__device__ __nv_bfloat16 g_wqh[(size_t)HD_ * E_],  g_wql[(size_t)HD_ * E_];
__device__ __nv_bfloat16 g_wkh[(size_t)KVD_ * E_], g_wkl[(size_t)KVD_ * E_];
__device__ __nv_bfloat16 g_wvh[(size_t)KVD_ * E_], g_wvl[(size_t)KVD_ * E_];
__device__ __nv_bfloat16 g_woh[(size_t)E_ * HD_],  g_wol[(size_t)E_ * HD_];
__device__ __nv_bfloat16 g_qh[(size_t)NTOK * HD_],  g_ql[(size_t)NTOK * HD_];
__device__ __nv_bfloat16 g_kh[(size_t)NTOK * KVD_], g_kl[(size_t)NTOK * KVD_];
__device__ __nv_bfloat16 g_vh[(size_t)NTOK * KVD_], g_vl[(size_t)NTOK * KVD_];

// ---------------------------------------------------------------------------
// Primitives (base target, compile at compute_103)
// ---------------------------------------------------------------------------
__device__ __forceinline__ uint32_t smem_u32(const void* p) {
    uint32_t a;
    asm("{ .reg .u64 t; cvta.to.shared.u64 t, %1; cvt.u32.u64 %0, t; }" : "=r"(a) : "l"(p));
    return a;
}
__device__ __forceinline__ void ldsm4(uint32_t& r0, uint32_t& r1, uint32_t& r2,
                                      uint32_t& r3, uint32_t addr) {
    asm volatile("ldmatrix.sync.aligned.m8n8.x4.shared.b16 {%0,%1,%2,%3}, [%4];"
                 : "=r"(r0), "=r"(r1), "=r"(r2), "=r"(r3) : "r"(addr));
}
__device__ __forceinline__ void ldsm4t(uint32_t& r0, uint32_t& r1, uint32_t& r2,
                                       uint32_t& r3, uint32_t addr) {
    asm volatile("ldmatrix.sync.aligned.m8n8.x4.trans.shared.b16 {%0,%1,%2,%3}, [%4];"
                 : "=r"(r0), "=r"(r1), "=r"(r2), "=r"(r3) : "r"(addr));
}
__device__ __forceinline__ void mma_bf16(float* c, uint32_t a0, uint32_t a1,
                                         uint32_t a2, uint32_t a3,
                                         uint32_t b0, uint32_t b1) {
    asm volatile(
        "mma.sync.aligned.m16n8k16.row.col.f32.bf16.bf16.f32 "
        "{%0,%1,%2,%3}, {%4,%5,%6,%7}, {%8,%9}, {%0,%1,%2,%3};"
        : "+f"(c[0]), "+f"(c[1]), "+f"(c[2]), "+f"(c[3])
        : "r"(a0), "r"(a1), "r"(a2), "r"(a3), "r"(b0), "r"(b1));
}

// ---------------------------------------------------------------------------
// split: fp32 -> (hi, lo) bf16
// ---------------------------------------------------------------------------
__global__ __launch_bounds__(256) void split_kernel(
    const float* __restrict__ src, __nv_bfloat16* __restrict__ h,
    __nv_bfloat16* __restrict__ l, int n)
{
    int i = blockIdx.x * 256 + threadIdx.x;
    if (i < n) {
        float v = src[i];
        __nv_bfloat16 hh = __float2bfloat16(v);
        h[i] = hh;
        l[i] = __float2bfloat16(v - __bfloat162float(hh));
    }
}

// ---------------------------------------------------------------------------
// transpose + split: W [K][N] fp32 -> Th/Tl [N][K] bf16
// ---------------------------------------------------------------------------
__global__ __launch_bounds__(256) void transpose_split_kernel(
    const float* __restrict__ W, __nv_bfloat16* __restrict__ Th,
    __nv_bfloat16* __restrict__ Tl, int K, int N)
{
    __shared__ float t[32][33];
    int n = blockIdx.x * 32 + threadIdx.x;
    int k0 = blockIdx.y * 32;
    for (int j = threadIdx.y; j < 32; j += 8)
        t[j][threadIdx.x] = W[(size_t)(k0 + j) * N + n];
    __syncthreads();
    int k = k0 + threadIdx.x;
    for (int j = threadIdx.y; j < 32; j += 8) {
        float v = t[threadIdx.x][j];
        int nn = blockIdx.x * 32 + j;
        __nv_bfloat16 hh = __float2bfloat16(v);
        Th[(size_t)nn * K + k] = hh;
        Tl[(size_t)nn * K + k] = __float2bfloat16(v - __bfloat162float(hh));
    }
}

// ---------------------------------------------------------------------------
// HMMA GEMM (R5-verified synchronous mainloop, BK=64). 3-term split-bf16,
// fp32 accum. split_out: write (Ch,Cl) bf16 instead of fp32 C.
// ---------------------------------------------------------------------------
#define AS_B   144                 // 128B row + 16B pad
#define TILE_B (128 * AS_B)        // 18432
#define GSM_AH 0
#define GSM_AL (TILE_B)
#define GSM_BH (2 * TILE_B)
#define GSM_BL (3 * TILE_B)
#define GSM_TOTAL (4 * TILE_B)     // 73728

__global__ __launch_bounds__(256, 2) void gemm_hmma_kernel(
    const __nv_bfloat16* __restrict__ Ah, const __nv_bfloat16* __restrict__ Al,
    const __nv_bfloat16* __restrict__ Bh, const __nv_bfloat16* __restrict__ Bl,
    const float* __restrict__ bias, float* __restrict__ C,
    __nv_bfloat16* __restrict__ Ch, __nv_bfloat16* __restrict__ Cl,
    int M, int N, int K, int split_out)
{
    extern __shared__ char smem[];
    const uint32_t sbase = smem_u32(smem);
    const int tid  = threadIdx.x;
    const int wid  = tid >> 5, lane = tid & 31;
    const int m0   = blockIdx.y * 128, n0 = blockIdx.x * 128;
    const int wm   = (wid >> 2) * 64;
    const int wn   = (wid & 3) * 32;

    float acc[4][4][4];
#pragma unroll
    for (int i = 0; i < 4; i++)
#pragma unroll
        for (int j = 0; j < 4; j++)
#pragma unroll
            for (int f = 0; f < 4; f++) acc[i][j][f] = 0.f;

    const int lr  = tid >> 3;
    const int lcB = (tid & 7) << 4;

    const int a_row = wm + (lane & 7) + ((lane >> 3) & 1) * 8;
    const int a_kB  = (lane >> 4) * 16;
    const int seg   = lane >> 3;
    const int b_row = wn + (lane & 7) + (seg >> 1) * 8;
    const int b_kB  = (seg & 1) * 16;

    for (int k0 = 0; k0 < K; k0 += 64) {
#pragma unroll
        for (int t = 0; t < 4; t++) {
            int r = lr + t * 32;
            size_t ga = ((size_t)(m0 + r) * K + k0) * 2 + lcB;
            size_t gb = ((size_t)(n0 + r) * K + k0) * 2 + lcB;
            int so = r * AS_B + lcB;
            *(uint4*)(smem + GSM_AH + so) = *(const uint4*)((const char*)Ah + ga);
            *(uint4*)(smem + GSM_AL + so) = *(const uint4*)((const char*)Al + ga);
            *(uint4*)(smem + GSM_BH + so) = *(const uint4*)((const char*)Bh + gb);
            *(uint4*)(smem + GSM_BL + so) = *(const uint4*)((const char*)Bl + gb);
        }
        __syncthreads();

#pragma unroll
        for (int ks = 0; ks < 4; ks++) {
            const int kB = ks * 32;
            uint32_t af[4][4], bh[4][2], bl[4][2];
#pragma unroll
            for (int mt = 0; mt < 4; mt++)
                ldsm4(af[mt][0], af[mt][1], af[mt][2], af[mt][3],
                      sbase + GSM_AH + (a_row + mt * 16) * AS_B + kB + a_kB);
#pragma unroll
            for (int bt = 0; bt < 2; bt++) {
                uint32_t r0, r1, r2, r3;
                ldsm4(r0, r1, r2, r3,
                      sbase + GSM_BH + (b_row + bt * 16) * AS_B + kB + b_kB);
                bh[bt * 2][0] = r0; bh[bt * 2][1] = r1;
                bh[bt * 2 + 1][0] = r2; bh[bt * 2 + 1][1] = r3;
            }
#pragma unroll
            for (int mt = 0; mt < 4; mt++)
#pragma unroll
                for (int nt = 0; nt < 4; nt++)
                    mma_bf16(acc[mt][nt], af[mt][0], af[mt][1], af[mt][2],
                             af[mt][3], bh[nt][0], bh[nt][1]);
#pragma unroll
            for (int bt = 0; bt < 2; bt++) {
                uint32_t r0, r1, r2, r3;
                ldsm4(r0, r1, r2, r3,
                      sbase + GSM_BL + (b_row + bt * 16) * AS_B + kB + b_kB);
                bl[bt * 2][0] = r0; bl[bt * 2][1] = r1;
                bl[bt * 2 + 1][0] = r2; bl[bt * 2 + 1][1] = r3;
            }
#pragma unroll
            for (int mt = 0; mt < 4; mt++)
#pragma unroll
                for (int nt = 0; nt < 4; nt++)
                    mma_bf16(acc[mt][nt], af[mt][0], af[mt][1], af[mt][2],
                             af[mt][3], bl[nt][0], bl[nt][1]);
#pragma unroll
            for (int mt = 0; mt < 4; mt++)
                ldsm4(af[mt][0], af[mt][1], af[mt][2], af[mt][3],
                      sbase + GSM_AL + (a_row + mt * 16) * AS_B + kB + a_kB);
#pragma unroll
            for (int mt = 0; mt < 4; mt++)
#pragma unroll
                for (int nt = 0; nt < 4; nt++)
                    mma_bf16(acc[mt][nt], af[mt][0], af[mt][1], af[mt][2],
                             af[mt][3], bh[nt][0], bh[nt][1]);
        }
        __syncthreads();
    }

#pragma unroll
    for (int nt = 0; nt < 4; nt++) {
        int col = n0 + wn + nt * 8 + (lane & 3) * 2;
        float b0 = bias ? bias[col] : 0.f;
        float b1 = bias ? bias[col + 1] : 0.f;
#pragma unroll
        for (int mt = 0; mt < 4; mt++) {
            int row = m0 + wm + mt * 16 + (lane >> 2);
            float v00 = acc[mt][nt][0] + b0, v01 = acc[mt][nt][1] + b1;
            float v10 = acc[mt][nt][2] + b0, v11 = acc[mt][nt][3] + b1;
            if (!split_out) {
                *(float2*)(C + (size_t)row * N + col) = make_float2(v00, v01);
                *(float2*)(C + (size_t)(row + 8) * N + col) = make_float2(v10, v11);
            } else {
                __nv_bfloat16 h00 = __float2bfloat16(v00), h01 = __float2bfloat16(v01);
                __nv_bfloat16 h10 = __float2bfloat16(v10), h11 = __float2bfloat16(v11);
                *(__nv_bfloat162*)(Ch + (size_t)row * N + col) = __nv_bfloat162(h00, h01);
                *(__nv_bfloat162*)(Ch + (size_t)(row + 8) * N + col) = __nv_bfloat162(h10, h11);
                *(__nv_bfloat162*)(Cl + (size_t)row * N + col) =
                    __nv_bfloat162(__float2bfloat16(v00 - __bfloat162float(h00)),
                                   __float2bfloat16(v01 - __bfloat162float(h01)));
                *(__nv_bfloat162*)(Cl + (size_t)(row + 8) * N + col) =
                    __nv_bfloat162(__float2bfloat16(v10 - __bfloat162float(h10)),
                                   __float2bfloat16(v11 - __bfloat162float(h11)));
            }
        }
    }
}

// ---------------------------------------------------------------------------
// Fused RMSNorm + RoPE -> split-bf16 output
// ---------------------------------------------------------------------------
__global__ __launch_bounds__(256) void rmsrope_split_kernel(
    const float* __restrict__ t, const float* __restrict__ cosT,
    const float* __restrict__ sinT, const float* __restrict__ scale, int heads,
    __nv_bfloat16* __restrict__ oh, __nv_bfloat16* __restrict__ ol)
{
    int gw   = (blockIdx.x * 256 + threadIdx.x) >> 5;
    int lane = threadIdx.x & 31;
    if (gw >= NTOK * heads) return;
    int token = gw / heads;
    int h     = gw - token * heads;
    int s     = token & (S_ - 1);

    const float* row = t + ((size_t)token * heads + h) * D_;
    float4 x = *(const float4*)(row + lane * 4);

    float ss = fmaf(x.x, x.x, fmaf(x.y, x.y, fmaf(x.z, x.z, x.w * x.w)));
#pragma unroll
    for (int o = 16; o; o >>= 1) ss += __shfl_xor_sync(0xffffffffu, ss, o);
    float r = rsqrtf(ss * (1.0f / D_) + 1e-6f);

    float4 sc = *(const float4*)(scale + lane * 4);
    float4 y;
    y.x = x.x * r * sc.x; y.y = x.y * r * sc.y;
    y.z = x.z * r * sc.z; y.w = x.w * r * sc.w;

    float4 p;
    p.x = __shfl_xor_sync(0xffffffffu, y.x, 16);
    p.y = __shfl_xor_sync(0xffffffffu, y.y, 16);
    p.z = __shfl_xor_sync(0xffffffffu, y.z, 16);
    p.w = __shfl_xor_sync(0xffffffffu, y.w, 16);

    float4 c  = *(const float4*)(cosT + (size_t)s * D_ + lane * 4);
    float4 sn = *(const float4*)(sinT + (size_t)s * D_ + lane * 4);
    float sg  = (lane < 16) ? -1.f : 1.f;

    float o0 = fmaf(y.x, c.x, sg * p.x * sn.x);
    float o1 = fmaf(y.y, c.y, sg * p.y * sn.y);
    float o2 = fmaf(y.z, c.z, sg * p.z * sn.z);
    float o3 = fmaf(y.w, c.w, sg * p.w * sn.w);

    size_t off = ((size_t)token * heads + h) * D_ + lane * 4;
    __nv_bfloat16 h0 = __float2bfloat16(o0), h1 = __float2bfloat16(o1);
    __nv_bfloat16 h2 = __float2bfloat16(o2), h3 = __float2bfloat16(o3);
    *(__nv_bfloat162*)(oh + off)     = __nv_bfloat162(h0, h1);
    *(__nv_bfloat162*)(oh + off + 2) = __nv_bfloat162(h2, h3);
    *(__nv_bfloat162*)(ol + off) =
        __nv_bfloat162(__float2bfloat16(o0 - __bfloat162float(h0)),
                       __float2bfloat16(o1 - __bfloat162float(h1)));
    *(__nv_bfloat162*)(ol + off + 2) =
        __nv_bfloat162(__float2bfloat16(o2 - __bfloat162float(h2)),
                       __float2bfloat16(o3 - __bfloat162float(h3)));
}

// ---------------------------------------------------------------------------
// Flash attention, HMMA bf16 3-term split, causal, GQA.
// 64 q-rows/block, k-tiles of 64, 8 warps. K and V SHARE one smem buffer
// (K loaded, QK^T, then V overwrites while softmax runs) -> 105.7KB smem
// -> 2 CTAs/SM. Writes split-bf16 ctx.
// ---------------------------------------------------------------------------
#define QK_STRIDE 272
#define P_STRIDE  144
#define ASM_QH  0
#define ASM_QL  (ASM_QH + 64 * QK_STRIDE)
#define ASM_KVH (ASM_QL + 64 * QK_STRIDE)
#define ASM_KVL (ASM_KVH + 64 * QK_STRIDE)
#define ASM_PH  (ASM_KVL + 64 * QK_STRIDE)
#define ASM_PL  (ASM_PH + 64 * P_STRIDE)
#define ASM_S   (ASM_PL + 64 * P_STRIDE)
#define ASM_M   (ASM_S + 64 * 66 * 4)
#define ASM_L   (ASM_M + 256)
#define ASM_F   (ASM_L + 256)
#define ASM_TOTAL (ASM_F + 256)       // 105,728 B -> occupancy 2

__global__ __launch_bounds__(256, 2) void attn_hmma_kernel(
    const __nv_bfloat16* __restrict__ qh, const __nv_bfloat16* __restrict__ ql,
    const __nv_bfloat16* __restrict__ kh, const __nv_bfloat16* __restrict__ kl,
    const __nv_bfloat16* __restrict__ vh, const __nv_bfloat16* __restrict__ vl,
    __nv_bfloat16* __restrict__ ch, __nv_bfloat16* __restrict__ cl)
{
    extern __shared__ char smem[];
    const uint32_t sbase = smem_u32(smem);
    float* sS = (float*)(smem + ASM_S);
    float* sM = (float*)(smem + ASM_M);
    float* sL = (float*)(smem + ASM_L);
    float* sF = (float*)(smem + ASM_F);

    const int tid = threadIdx.x, wid = tid >> 5, lane = tid & 31;
    const int qt = blockIdx.x, h = blockIdx.y, b = blockIdx.z;
    const int kvh  = h >> 2;
    const int tok0 = b * S_ + qt * 64;

    const int mr = wid & 3;
    const int nc = wid >> 2;

    for (int i = tid; i < 64 * 16; i += 256) {
        int r = i >> 4, c = i & 15;
        size_t g = (size_t)(tok0 + r) * HD_ + h * D_ + c * 8;
        *(uint4*)(smem + ASM_QH + r * QK_STRIDE + c * 16) = *(const uint4*)(qh + g);
        *(uint4*)(smem + ASM_QL + r * QK_STRIDE + c * 16) = *(const uint4*)(ql + g);
    }
    if (tid < 64) { sM[tid] = -FLT_MAX; sL[tid] = 0.f; }

    float ctxacc[8][4];
#pragma unroll
    for (int i = 0; i < 8; i++)
#pragma unroll
        for (int f = 0; f < 4; f++) ctxacc[i][f] = 0.f;

    const int a_row = (lane & 7) + ((lane >> 3) & 1) * 8;
    const int a_kB  = (lane >> 4) * 16;
    const int seg   = lane >> 3;
    const int b_row = (lane & 7) + (seg >> 1) * 8;
    const int b_kB  = (seg & 1) * 16;
    const int t_row = (lane & 7) + (seg & 1) * 8;
    const int t_cB  = (seg >> 1) * 16;

    const float rsc = 0.08838834764831845f;
    const int row_a = mr * 16 + (lane >> 2);

    for (int kt = 0; kt <= qt; kt++) {
        const int ktok0 = b * S_ + kt * 64;
        __syncthreads();  // prev PV done -> safe to overwrite KV buffer with K
        for (int i = tid; i < 64 * 16; i += 256) {
            int r = i >> 4, c = i & 15;
            size_t g = (size_t)(ktok0 + r) * KVD_ + kvh * D_ + c * 8;
            *(uint4*)(smem + ASM_KVH + r * QK_STRIDE + c * 16) = *(const uint4*)(kh + g);
            *(uint4*)(smem + ASM_KVL + r * QK_STRIDE + c * 16) = *(const uint4*)(kl + g);
        }
        __syncthreads();

        // ---- QK^T ----
        float sacc[4][4];
#pragma unroll
        for (int i = 0; i < 4; i++)
#pragma unroll
            for (int f = 0; f < 4; f++) sacc[i][f] = 0.f;

#pragma unroll
        for (int ks = 0; ks < 8; ks++) {
            const int kB = ks * 32;
            uint32_t ah[4], al[4];
            ldsm4(ah[0], ah[1], ah[2], ah[3],
                  sbase + ASM_QH + (mr * 16 + a_row) * QK_STRIDE + kB + a_kB);
            ldsm4(al[0], al[1], al[2], al[3],
                  sbase + ASM_QL + (mr * 16 + a_row) * QK_STRIDE + kB + a_kB);
#pragma unroll
            for (int bt = 0; bt < 2; bt++) {
                uint32_t r0, r1, r2, r3;
                ldsm4(r0, r1, r2, r3,
                      sbase + ASM_KVH + (nc * 32 + bt * 16 + b_row) * QK_STRIDE + kB + b_kB);
                mma_bf16(sacc[bt * 2],     ah[0], ah[1], ah[2], ah[3], r0, r1);
                mma_bf16(sacc[bt * 2 + 1], ah[0], ah[1], ah[2], ah[3], r2, r3);
                mma_bf16(sacc[bt * 2],     al[0], al[1], al[2], al[3], r0, r1);
                mma_bf16(sacc[bt * 2 + 1], al[0], al[1], al[2], al[3], r2, r3);
                uint32_t s0, s1, s2, s3;
                ldsm4(s0, s1, s2, s3,
                      sbase + ASM_KVL + (nc * 32 + bt * 16 + b_row) * QK_STRIDE + kB + b_kB);
                mma_bf16(sacc[bt * 2],     ah[0], ah[1], ah[2], ah[3], s0, s1);
                mma_bf16(sacc[bt * 2 + 1], ah[0], ah[1], ah[2], ah[3], s2, s3);
            }
        }
#pragma unroll
        for (int nt = 0; nt < 4; nt++) {
            int col = nc * 32 + nt * 8 + (lane & 3) * 2;
            *(float2*)&sS[row_a * 66 + col] =
                make_float2(sacc[nt][0] * rsc, sacc[nt][1] * rsc);
            *(float2*)&sS[(row_a + 8) * 66 + col] =
                make_float2(sacc[nt][2] * rsc, sacc[nt][3] * rsc);
        }
        __syncthreads();  // S published; all K reads done -> buffer reusable

        // ---- load V into the shared KV buffer (overwrite K), then softmax;
        //      no barrier between them so warps overlap the two phases ----
        for (int i = tid; i < 64 * 16; i += 256) {
            int r = i >> 4, c = i & 15;
            size_t g = (size_t)(ktok0 + r) * KVD_ + kvh * D_ + c * 8;
            *(uint4*)(smem + ASM_KVH + r * QK_STRIDE + c * 16) = *(const uint4*)(vh + g);
            *(uint4*)(smem + ASM_KVL + r * QK_STRIDE + c * 16) = *(const uint4*)(vl + g);
        }
        {
            const int r = tid >> 2, q4 = tid & 3;
            const int j0 = q4 * 16;
            const bool diag = (kt == qt);
            float mold = sM[r];
            float sv[16];
            float tm = -FLT_MAX;
#pragma unroll
            for (int jj = 0; jj < 16; jj++) {
                float v = sS[r * 66 + j0 + jj];
                if (diag && (j0 + jj) > r) v = -FLT_MAX;
                sv[jj] = v;
                tm = fmaxf(tm, v);
            }
            tm = fmaxf(tm, __shfl_xor_sync(0xffffffffu, tm, 1));
            tm = fmaxf(tm, __shfl_xor_sync(0xffffffffu, tm, 2));
            tm = fmaxf(tm, mold);
            float ps = 0.f;
            __nv_bfloat16* ph = (__nv_bfloat16*)(smem + ASM_PH + r * P_STRIDE) + j0;
            __nv_bfloat16* pl = (__nv_bfloat16*)(smem + ASM_PL + r * P_STRIDE) + j0;
#pragma unroll
            for (int jj = 0; jj < 16; jj++) {
                float p = __expf(sv[jj] - tm);
                ps += p;
                __nv_bfloat16 hh = __float2bfloat16(p);
                ph[jj] = hh;
                pl[jj] = __float2bfloat16(p - __bfloat162float(hh));
            }
            ps += __shfl_xor_sync(0xffffffffu, ps, 1);
            ps += __shfl_xor_sync(0xffffffffu, ps, 2);
            if (q4 == 0) {
                float fsc = __expf(mold - tm);
                sM[r] = tm;
                sL[r] = sL[r] * fsc + ps;
                sF[r] = fsc;
            }
        }
        __syncthreads();  // V + P + F visible

        // ---- rescale ctx accs, then PV ----
        {
            float f0 = sF[row_a], f1 = sF[row_a + 8];
#pragma unroll
            for (int nt = 0; nt < 8; nt++) {
                ctxacc[nt][0] *= f0; ctxacc[nt][1] *= f0;
                ctxacc[nt][2] *= f1; ctxacc[nt][3] *= f1;
            }
        }
#pragma unroll
        for (int ks = 0; ks < 4; ks++) {
            const int kB = ks * 32;
            uint32_t ph4[4], pl4[4];
            ldsm4(ph4[0], ph4[1], ph4[2], ph4[3],
                  sbase + ASM_PH + (mr * 16 + a_row) * P_STRIDE + kB + a_kB);
            ldsm4(pl4[0], pl4[1], pl4[2], pl4[3],
                  sbase + ASM_PL + (mr * 16 + a_row) * P_STRIDE + kB + a_kB);
#pragma unroll
            for (int bt = 0; bt < 4; bt++) {
                uint32_t r0, r1, r2, r3;
                ldsm4t(r0, r1, r2, r3,
                       sbase + ASM_KVH + (ks * 16 + t_row) * QK_STRIDE
                             + nc * 128 + bt * 32 + t_cB);
                mma_bf16(ctxacc[bt * 2],     ph4[0], ph4[1], ph4[2], ph4[3], r0, r1);
                mma_bf16(ctxacc[bt * 2 + 1], ph4[0], ph4[1], ph4[2], ph4[3], r2, r3);
                mma_bf16(ctxacc[bt * 2],     pl4[0], pl4[1], pl4[2], pl4[3], r0, r1);
                mma_bf16(ctxacc[bt * 2 + 1], pl4[0], pl4[1], pl4[2], pl4[3], r2, r3);
                uint32_t s0, s1, s2, s3;
                ldsm4t(s0, s1, s2, s3,
                       sbase + ASM_KVL + (ks * 16 + t_row) * QK_STRIDE
                             + nc * 128 + bt * 32 + t_cB);
                mma_bf16(ctxacc[bt * 2],     ph4[0], ph4[1], ph4[2], ph4[3], s0, s1);
                mma_bf16(ctxacc[bt * 2 + 1], ph4[0], ph4[1], ph4[2], ph4[3], s2, s3);
            }
        }
    }

    __syncthreads();
    const float inv0 = 1.0f / sL[row_a];
    const float inv1 = 1.0f / sL[row_a + 8];
#pragma unroll
    for (int nt = 0; nt < 8; nt++) {
        int col = nc * 64 + nt * 8 + (lane & 3) * 2;
        size_t o0 = (size_t)(tok0 + row_a) * HD_ + h * D_ + col;
        size_t o1 = (size_t)(tok0 + row_a + 8) * HD_ + h * D_ + col;
        float v00 = ctxacc[nt][0] * inv0, v01 = ctxacc[nt][1] * inv0;
        float v10 = ctxacc[nt][2] * inv1, v11 = ctxacc[nt][3] * inv1;
        __nv_bfloat16 h00 = __float2bfloat16(v00), h01 = __float2bfloat16(v01);
        __nv_bfloat16 h10 = __float2bfloat16(v10), h11 = __float2bfloat16(v11);
        *(__nv_bfloat162*)(ch + o0) = __nv_bfloat162(h00, h01);
        *(__nv_bfloat162*)(ch + o1) = __nv_bfloat162(h10, h11);
        *(__nv_bfloat162*)(cl + o0) =
            __nv_bfloat162(__float2bfloat16(v00 - __bfloat162float(h00)),
                           __float2bfloat16(v01 - __bfloat162float(h01)));
        *(__nv_bfloat162*)(cl + o1) =
            __nv_bfloat162(__float2bfloat16(v10 - __bfloat162float(h10)),
                           __float2bfloat16(v11 - __bfloat162float(h11)));
    }
}

// ---------------------------------------------------------------------------
// Inputs: 0:x 1:mask 2:cos 3:sin 4:Wq 5:bq 6:Wk 7:bk 8:Wv 9:bv 10:Wo 11:qs 12:ks
// ---------------------------------------------------------------------------
extern "C" void kernel_launch(void* const* d_in, const int* in_sizes, int n_in,
                              void* d_out, int out_size)
{
    const float* x    = (const float*)d_in[0];
    const float* cosT = (const float*)d_in[2];
    const float* sinT = (const float*)d_in[3];
    const float* Wq   = (const float*)d_in[4];
    const float* bq   = (const float*)d_in[5];
    const float* Wk   = (const float*)d_in[6];
    const float* bk   = (const float*)d_in[7];
    const float* Wv   = (const float*)d_in[8];
    const float* bv   = (const float*)d_in[9];
    const float* Wo   = (const float*)d_in[10];
    const float* qs   = (const float*)d_in[11];
    const float* ks   = (const float*)d_in[12];
    float* out = (float*)d_out;
    (void)in_sizes; (void)n_in; (void)out_size;

    float *dq, *dk;
    cudaGetSymbolAddress((void**)&dq, g_q);
    cudaGetSymbolAddress((void**)&dk, g_k);
    __nv_bfloat16 *xh, *xl, *ch, *cl, *wqh, *wql, *wkh, *wkl, *wvh, *wvl, *woh, *wol;
    __nv_bfloat16 *aqh, *aql, *akh, *akl, *avh, *avl;
    cudaGetSymbolAddress((void**)&xh, g_xh);   cudaGetSymbolAddress((void**)&xl, g_xl);
    cudaGetSymbolAddress((void**)&ch, g_ch);   cudaGetSymbolAddress((void**)&cl, g_cl);
    cudaGetSymbolAddress((void**)&wqh, g_wqh); cudaGetSymbolAddress((void**)&wql, g_wql);
    cudaGetSymbolAddress((void**)&wkh, g_wkh); cudaGetSymbolAddress((void**)&wkl, g_wkl);
    cudaGetSymbolAddress((void**)&wvh, g_wvh); cudaGetSymbolAddress((void**)&wvl, g_wvl);
    cudaGetSymbolAddress((void**)&woh, g_woh); cudaGetSymbolAddress((void**)&wol, g_wol);
    cudaGetSymbolAddress((void**)&aqh, g_qh);  cudaGetSymbolAddress((void**)&aql, g_ql);
    cudaGetSymbolAddress((void**)&akh, g_kh);  cudaGetSymbolAddress((void**)&akl, g_kl);
    cudaGetSymbolAddress((void**)&avh, g_vh);  cudaGetSymbolAddress((void**)&avl, g_vl);

    cudaFuncSetAttribute(attn_hmma_kernel, cudaFuncAttributeMaxDynamicSharedMemorySize,
                         ASM_TOTAL);
    cudaFuncSetAttribute(gemm_hmma_kernel, cudaFuncAttributeMaxDynamicSharedMemorySize,
                         GSM_TOTAL);

    dim3 t256(256);
    dim3 t32x8(32, 8);

    split_kernel<<<(NTOK * E_) / 256, t256>>>(x, xh, xl, NTOK * E_);
    transpose_split_kernel<<<dim3(HD_ / 32, E_ / 32), t32x8>>>(Wq, wqh, wql, E_, HD_);
    transpose_split_kernel<<<dim3(KVD_ / 32, E_ / 32), t32x8>>>(Wk, wkh, wkl, E_, KVD_);
    transpose_split_kernel<<<dim3(KVD_ / 32, E_ / 32), t32x8>>>(Wv, wvh, wvl, E_, KVD_);
    // projections (V writes split bf16 directly)
    gemm_hmma_kernel<<<dim3(HD_ / 128, NTOK / 128), t256, GSM_TOTAL>>>(
        xh, xl, wqh, wql, bq, dq, nullptr, nullptr, NTOK, HD_, E_, 0);
    gemm_hmma_kernel<<<dim3(KVD_ / 128, NTOK / 128), t256, GSM_TOTAL>>>(
        xh, xl, wkh, wkl, bk, dk, nullptr, nullptr, NTOK, KVD_, E_, 0);
    gemm_hmma_kernel<<<dim3(KVD_ / 128, NTOK / 128), t256, GSM_TOTAL>>>(
        xh, xl, wvh, wvl, bv, nullptr, avh, avl, NTOK, KVD_, E_, 1);
    transpose_split_kernel<<<dim3(E_ / 32, HD_ / 32), t32x8>>>(Wo, woh, wol, HD_, E_);
    // RMSNorm + RoPE -> split bf16
    rmsrope_split_kernel<<<(NTOK * H_ * 32) / 256, t256>>>(dq, cosT, sinT, qs, H_, aqh, aql);
    rmsrope_split_kernel<<<(NTOK * KV_ * 32) / 256, t256>>>(dk, cosT, sinT, ks, KV_, akh, akl);
    // attention -> split bf16 ctx
    attn_hmma_kernel<<<dim3(S_ / 64, H_, B_), t256, ASM_TOTAL>>>(
        aqh, aql, akh, akl, avh, avl, ch, cl);
    // output projection
    gemm_hmma_kernel<<<dim3(E_ / 128, NTOK / 128), t256, GSM_TOTAL>>>(
        ch, cl, woh, wol, nullptr, out, nullptr, nullptr, NTOK, E_, HD_, 0);
}